// round 2
// baseline (speedup 1.0000x reference)
#include <cuda_runtime.h>

// Problem dims
#define NB 16
#define NS 2048
#define ND 64
#define NO 128

// Kernel-1 split-K
#define SPLIT 16
#define KCH (NS / SPLIT)   // 128
#define KT 32

// k2 smem geometry
#define XROW 66            // float2 per x row (64 + pad 2)
#define YROW 132           // floats per Yt row (128 + pad 4)

// Scratch (allocation-free rule: __device__ globals)
__device__ float g_Ypart[SPLIT * NB * NO * ND];   // 8 MB
__device__ float g_Y[NB * NO * ND];               // 512 KB

// ---- packed f32x2 helpers -------------------------------------------------
__device__ __forceinline__ unsigned long long ffma2(unsigned long long a,
                                                    unsigned long long b,
                                                    unsigned long long c) {
    unsigned long long d;
    asm("fma.rn.f32x2 %0, %1, %2, %3;" : "=l"(d) : "l"(a), "l"(b), "l"(c));
    return d;
}
__device__ __forceinline__ float2 unpack2(unsigned long long v) {
    float2 f;
    asm("mov.b64 {%0, %1}, %2;" : "=f"(f.x), "=f"(f.y) : "l"(v));
    return f;
}

// ---------------------------------------------------------------------------
// Kernel 1: Ypart[sp][b][o][d] = sum_{k in chunk} W[o,k] * x[b,k,d]
// grid (NB, SPLIT), 256 threads. Tile 128(o) x 64(d). f32x2 packed along d.
// ---------------------------------------------------------------------------
__global__ __launch_bounds__(256) void k1_partial(const float* __restrict__ x,
                                                  const float* __restrict__ W) {
    __shared__ float2 Ws2[KT][NO + 1];   // (w,w) duplicated, pad breaks STS conflicts
    __shared__ float  Xs[KT][ND];

    const int b   = blockIdx.x;
    const int sp  = blockIdx.y;
    const int tid = threadIdx.x;
    const int kbase0 = sp * KCH;

    unsigned long long acc[8][2];
#pragma unroll
    for (int i = 0; i < 8; i++) { acc[i][0] = 0ULL; acc[i][1] = 0ULL; }

    const int o0 = (tid >> 4) * 8;     // 0..120 step 8
    const int d0 = (tid & 15) * 4;     // 0..60  step 4

    for (int kt = 0; kt < KCH; kt += KT) {
        const int kbase = kbase0 + kt;
        // W tile 32k x 128o, coalesced gmem, duplicated store
#pragma unroll
        for (int j = 0; j < 16; j++) {
            int idx = tid + j * 256;
            int o = idx >> 5, kk = idx & 31;
            float w = W[o * NS + kbase + kk];
            Ws2[kk][o] = make_float2(w, w);
        }
        // X tile 32k x 64d, coalesced
#pragma unroll
        for (int j = 0; j < 8; j++) {
            int idx = tid + j * 256;
            int kk = idx >> 6, d = idx & 63;
            Xs[kk][d] = x[(size_t)b * NS * ND + (size_t)(kbase + kk) * ND + d];
        }
        __syncthreads();

#pragma unroll 8
        for (int k = 0; k < KT; k++) {
            ulonglong2 xv = *(const ulonglong2*)&Xs[k][d0];  // 2 f32x2 (unique d pairs)
#pragma unroll
            for (int i = 0; i < 8; i++) {
                unsigned long long w2 =
                    *(const unsigned long long*)&Ws2[k][o0 + i];  // (w,w) broadcast
                acc[i][0] = ffma2(w2, xv.x, acc[i][0]);
                acc[i][1] = ffma2(w2, xv.y, acc[i][1]);
            }
        }
        __syncthreads();
    }

    float* dst = &g_Ypart[((size_t)(sp * NB + b) * NO) * ND];
#pragma unroll
    for (int i = 0; i < 8; i++) {
        float2 p0 = unpack2(acc[i][0]);
        float2 p1 = unpack2(acc[i][1]);
        *(float4*)&dst[(o0 + i) * ND + d0] = make_float4(p0.x, p0.y, p1.x, p1.y);
    }
}

// ---------------------------------------------------------------------------
// Kernel 1b: reduce SPLIT partials
// ---------------------------------------------------------------------------
__global__ __launch_bounds__(256) void k1_reduce() {
    int e = blockIdx.x * 256 + threadIdx.x;
    const float4* src = (const float4*)g_Ypart;
    const int stride = NB * NO * ND / 4;
    float4 s = src[e];
#pragma unroll
    for (int p = 1; p < SPLIT; p++) {
        float4 v = src[(size_t)p * stride + e];
        s.x += v.x; s.y += v.y; s.z += v.z; s.w += v.w;
    }
    ((float4*)g_Y)[e] = s;
}

// ---------------------------------------------------------------------------
// Kernel 2: out[b,s,o] = sum_d x[b,s,d] * Y[b,o,d] + bias[o]
// grid (16 s-tiles, NB), 256 threads, 128x128 tile, K=64.
// f32x2 packed along o: Yt[d][o] transposed (unique o pairs), Xs2 duplicated.
// ---------------------------------------------------------------------------
__global__ __launch_bounds__(256) void k2(const float* __restrict__ x,
                                          const float* __restrict__ bias,
                                          float* __restrict__ out) {
    extern __shared__ float sm[];
    float2* Xs2 = (float2*)sm;               // [128][XROW] float2, (x,x) dup
    float*  Yt  = sm + 128 * XROW * 2;       // [64][YROW] floats, transposed

    const int st  = blockIdx.x;
    const int b   = blockIdx.y;
    const int tid = threadIdx.x;
    const int s0  = st * 128;

    // Load X tile [128 s][64 d], duplicated as (x,x) pairs
    const float4* xg = (const float4*)&x[((size_t)b * NS + s0) * ND];
#pragma unroll
    for (int j = 0; j < 8; j++) {
        int idx = tid + j * 256;
        int s = idx >> 4, d4 = idx & 15;
        float4 v = xg[idx];
        float2* p = &Xs2[s * XROW + d4 * 4];
        *(float4*)(p + 0) = make_float4(v.x, v.x, v.y, v.y);
        *(float4*)(p + 2) = make_float4(v.z, v.z, v.w, v.w);
    }
    // Load + transpose Y tile: Yt[d][o] = Y[b][o][d]
    const float* yg = &g_Y[(size_t)b * NO * ND];
#pragma unroll
    for (int j = 0; j < 32; j++) {
        int idx = tid + j * 256;
        int o = idx >> 6, d = idx & 63;
        Yt[d * YROW + o] = yg[idx];
    }
    __syncthreads();

    const int sg = tid >> 4;        // s rows: sg + 16*i
    const int o0 = (tid & 15) * 8;  // o cols: o0 .. o0+7 (4 adjacent pairs)

    unsigned long long acc[8][4];
#pragma unroll
    for (int i = 0; i < 8; i++)
#pragma unroll
        for (int j = 0; j < 4; j++) acc[i][j] = 0ULL;

#pragma unroll 8
    for (int d = 0; d < ND; d += 2) {
        const float* yr0 = &Yt[d * YROW + o0];
        ulonglong2 ya = *(const ulonglong2*)yr0;        // d:   (o0,o0+1),(o0+2,o0+3)
        ulonglong2 yb = *(const ulonglong2*)(yr0 + 4);  // d:   (o0+4..o0+7)
        ulonglong2 yc = *(const ulonglong2*)(yr0 + YROW);
        ulonglong2 yd = *(const ulonglong2*)(yr0 + YROW + 4);
#pragma unroll
        for (int i = 0; i < 8; i++) {
            ulonglong2 xv = *(const ulonglong2*)&Xs2[(sg + 16 * i) * XROW + d];
            acc[i][0] = ffma2(xv.x, ya.x, acc[i][0]);
            acc[i][1] = ffma2(xv.x, ya.y, acc[i][1]);
            acc[i][2] = ffma2(xv.x, yb.x, acc[i][2]);
            acc[i][3] = ffma2(xv.x, yb.y, acc[i][3]);
            acc[i][0] = ffma2(xv.y, yc.x, acc[i][0]);
            acc[i][1] = ffma2(xv.y, yc.y, acc[i][1]);
            acc[i][2] = ffma2(xv.y, yd.x, acc[i][2]);
            acc[i][3] = ffma2(xv.y, yd.y, acc[i][3]);
        }
    }

    // Epilogue: +bias, float4 stores (o contiguous)
    float4 b0 = *(const float4*)&bias[o0];
    float4 b1 = *(const float4*)&bias[o0 + 4];
#pragma unroll
    for (int i = 0; i < 8; i++) {
        int s = s0 + sg + 16 * i;
        float2 p0 = unpack2(acc[i][0]);
        float2 p1 = unpack2(acc[i][1]);
        float2 p2 = unpack2(acc[i][2]);
        float2 p3 = unpack2(acc[i][3]);
        float* op = &out[((size_t)b * NS + s) * NO + o0];
        *(float4*)(op + 0) = make_float4(p0.x + b0.x, p0.y + b0.y,
                                         p1.x + b0.z, p1.y + b0.w);
        *(float4*)(op + 4) = make_float4(p2.x + b1.x, p2.y + b1.y,
                                         p3.x + b1.z, p3.y + b1.w);
    }
}

// ---------------------------------------------------------------------------
extern "C" void kernel_launch(void* const* d_in, const int* in_sizes, int n_in,
                              void* d_out, int out_size) {
    const float* x = nullptr;
    const float* W = nullptr;
    const float* bias = nullptr;
    for (int i = 0; i < n_in; i++) {
        if (in_sizes[i] == NB * NS * ND)      x = (const float*)d_in[i];
        else if (in_sizes[i] == NO * NS)      W = (const float*)d_in[i];
        else if (in_sizes[i] == NO)           bias = (const float*)d_in[i];
    }
    float* out = (float*)d_out;

    const int smem2 = (128 * XROW * 2 + 64 * YROW) * sizeof(float);  // 101376 B
    cudaFuncSetAttribute(k2, cudaFuncAttributeMaxDynamicSharedMemorySize, smem2);

    k1_partial<<<dim3(NB, SPLIT), 256>>>(x, W);
    k1_reduce<<<(NB * NO * ND / 4) / 256, 256>>>();
    k2<<<dim3(NS / 128, NB), 256, smem2>>>(x, bias, out);
}

// round 4
// speedup vs baseline: 1.5574x; 1.5574x over previous
#include <cuda_runtime.h>
#include <cuda_bf16.h>
#include <cstdint>

#define NB 16
#define NS 2048
#define ND 64
#define NO 128
#define KSPLIT 8
#define KC 256            // K per g1 block (2 stages of 128)

// ---------------- scratch (no allocs allowed) ------------------------------
__device__ float         g_Ypart[KSPLIT * NB * NO * ND];   // 4 MB fp32 partials
__device__ __nv_bfloat16 g_yhi[NB * NO * ND];              // Y hi [b][o][d]
__device__ __nv_bfloat16 g_ylo[NB * NO * ND];              // Y lo

// ---------------- helpers --------------------------------------------------
__device__ __forceinline__ uint32_t smem_u32(const void* p) {
    uint32_t a;
    asm("{ .reg .u64 t; cvta.to.shared.u64 t, %1; cvt.u32.u64 %0, t; }"
        : "=r"(a) : "l"(p));
    return a;
}
__device__ __forceinline__ void ldm_x4(uint32_t* r, uint32_t addr) {
    asm volatile("ldmatrix.sync.aligned.m8n8.x4.shared.b16 {%0,%1,%2,%3}, [%4];"
                 : "=r"(r[0]), "=r"(r[1]), "=r"(r[2]), "=r"(r[3]) : "r"(addr));
}
__device__ __forceinline__ void ldm_x4t(uint32_t* r, uint32_t addr) {
    asm volatile("ldmatrix.sync.aligned.m8n8.x4.trans.shared.b16 {%0,%1,%2,%3}, [%4];"
                 : "=r"(r[0]), "=r"(r[1]), "=r"(r[2]), "=r"(r[3]) : "r"(addr));
}
__device__ __forceinline__ void mma_bf16(float* c, const uint32_t* a,
                                         const uint32_t* b) {
    asm volatile(
        "mma.sync.aligned.m16n8k16.row.col.f32.bf16.bf16.f32 "
        "{%0,%1,%2,%3}, {%4,%5,%6,%7}, {%8,%9}, {%0,%1,%2,%3};"
        : "+f"(c[0]), "+f"(c[1]), "+f"(c[2]), "+f"(c[3])
        : "r"(a[0]), "r"(a[1]), "r"(a[2]), "r"(a[3]), "r"(b[0]), "r"(b[1]));
}
__device__ __forceinline__ uint32_t bpack2(float a, float b) {
    return (uint32_t)__bfloat16_as_ushort(__float2bfloat16(a)) |
           ((uint32_t)__bfloat16_as_ushort(__float2bfloat16(b)) << 16);
}
__device__ __forceinline__ float blo(float v) {
    return v - __bfloat162float(__float2bfloat16(v));
}

// ===========================================================================
// G1: Ypart[ks][b][o=128][d=64] = W[o, kslice] @ x[b, kslice, d]
// 3-term bf16 split via mma.sync. grid (KSPLIT, NB), 256 thr (8 warps 4x2).
// smem: WA [128 o][136 k] hi/lo (pitch 272B), XB [128 k][72 d] hi/lo (144B).
// ldmatrix rows shift 16B/row in bank space -> conflict-free.
// ===========================================================================
#define G1_WAHI 0
#define G1_WALO 34816
#define G1_XBHI 69632
#define G1_XBLO 88064
#define G1_SMEM 106496

__global__ __launch_bounds__(256) void g1(const float* __restrict__ x,
                                          const float* __restrict__ W) {
    extern __shared__ char sm[];
    const int tid = threadIdx.x, wid = tid >> 5, lane = tid & 31;
    const int ks = blockIdx.x, b = blockIdx.y;
    const int wm = wid & 3, wn = wid >> 2;
    const int o0 = wm * 32, d0 = wn * 32;

    const uint32_t s_wahi = smem_u32(sm + G1_WAHI);
    const uint32_t s_walo = smem_u32(sm + G1_WALO);
    const uint32_t s_xbhi = smem_u32(sm + G1_XBHI);
    const uint32_t s_xblo = smem_u32(sm + G1_XBLO);

    float acc[2][4][4];
#pragma unroll
    for (int mt = 0; mt < 2; mt++)
#pragma unroll
        for (int nt = 0; nt < 4; nt++)
#pragma unroll
            for (int q = 0; q < 4; q++) acc[mt][nt][q] = 0.f;

    for (int kt = 0; kt < 2; kt++) {
        const int kbase = ks * KC + kt * 128;
        // W tile [128 o][128 k] fp32 -> bf16 hi/lo
#pragma unroll
        for (int j = 0; j < 16; j++) {
            int idx = tid + j * 256;
            int o = idx >> 5, k4 = (idx & 31) * 4;
            float4 v = *(const float4*)(W + (size_t)o * NS + kbase + k4);
            *(uint2*)(sm + G1_WAHI + o * 272 + k4 * 2) =
                make_uint2(bpack2(v.x, v.y), bpack2(v.z, v.w));
            *(uint2*)(sm + G1_WALO + o * 272 + k4 * 2) =
                make_uint2(bpack2(blo(v.x), blo(v.y)), bpack2(blo(v.z), blo(v.w)));
        }
        // x tile [128 k][64 d] fp32 -> bf16 hi/lo
#pragma unroll
        for (int j = 0; j < 8; j++) {
            int idx = tid + j * 256;
            int k = idx >> 4, d4 = (idx & 15) * 4;
            float4 v = *(const float4*)(x + ((size_t)b * NS + kbase + k) * ND + d4);
            *(uint2*)(sm + G1_XBHI + k * 144 + d4 * 2) =
                make_uint2(bpack2(v.x, v.y), bpack2(v.z, v.w));
            *(uint2*)(sm + G1_XBLO + k * 144 + d4 * 2) =
                make_uint2(bpack2(blo(v.x), blo(v.y)), bpack2(blo(v.z), blo(v.w)));
        }
        __syncthreads();

#pragma unroll
        for (int kk = 0; kk < 8; kk++) {
            // A frags: 2 m-tiles, hi+lo
            uint32_t ahi[2][4], alo[2][4];
#pragma unroll
            for (int mt = 0; mt < 2; mt++) {
                uint32_t off = (uint32_t)((o0 + mt * 16 + (lane & 15)) * 272 +
                                          kk * 32 + (lane >> 4) * 16);
                ldm_x4(ahi[mt], s_wahi + off);
                ldm_x4(alo[mt], s_walo + off);
            }
            // B frags (trans from [k][d]): 2 pairs covering 4 n-tiles
            uint32_t bhi[2][4], blo_[2][4];
#pragma unroll
            for (int p = 0; p < 2; p++) {
                uint32_t off = (uint32_t)((kk * 16 + (lane & 15)) * 144 +
                                          (d0 + p * 16 + (lane >> 4) * 8) * 2);
                ldm_x4t(bhi[p], s_xbhi + off);
                ldm_x4t(blo_[p], s_xblo + off);
            }
#pragma unroll
            for (int mt = 0; mt < 2; mt++)
#pragma unroll
                for (int nt = 0; nt < 4; nt++) {
                    const uint32_t* bh = &bhi[nt >> 1][(nt & 1) * 2];
                    const uint32_t* bl = &blo_[nt >> 1][(nt & 1) * 2];
                    mma_bf16(acc[mt][nt], ahi[mt], bh);
                    mma_bf16(acc[mt][nt], ahi[mt], bl);
                    mma_bf16(acc[mt][nt], alo[mt], bh);
                }
        }
        __syncthreads();
    }

    // epilogue -> Ypart fp32
    float* Yp = g_Ypart + ((size_t)(ks * NB + b) * NO) * ND;
#pragma unroll
    for (int mt = 0; mt < 2; mt++)
#pragma unroll
        for (int nt = 0; nt < 4; nt++) {
            int o = o0 + mt * 16 + (lane >> 2);
            int d = d0 + nt * 8 + (lane & 3) * 2;
            float* p = Yp + (size_t)o * ND + d;
            *(float2*)p = make_float2(acc[mt][nt][0], acc[mt][nt][1]);
            *(float2*)(p + 8 * ND) = make_float2(acc[mt][nt][2], acc[mt][nt][3]);
        }
}

// ===========================================================================
// Reduce partials -> Y bf16 hi/lo
// ===========================================================================
__global__ __launch_bounds__(256) void yred() {
    int e = blockIdx.x * 256 + threadIdx.x;   // float4 idx, 32768 total
    const float4* src = (const float4*)g_Ypart;
    const int stride = NB * NO * ND / 4;
    float4 s = src[e];
#pragma unroll
    for (int p = 1; p < KSPLIT; p++) {
        float4 v = src[(size_t)p * stride + e];
        s.x += v.x; s.y += v.y; s.z += v.z; s.w += v.w;
    }
    int base = e * 4;
    *(uint2*)&g_yhi[base] = make_uint2(bpack2(s.x, s.y), bpack2(s.z, s.w));
    *(uint2*)&g_ylo[base] = make_uint2(bpack2(blo(s.x), blo(s.y)),
                                       bpack2(blo(s.z), blo(s.w)));
}

// ===========================================================================
// G2: out[b][s][o] = x[b,s,:] . Y[b,o,:] + bias[o]
// grid (NS/64, NB) = 512 blocks, 256 thr (8 warps: 4 s x 2 o).
// Tile M=64 s, N=128 o, K=64. smem: XS [64][72] hi/lo, YS [128][72] hi/lo.
// ===========================================================================
#define G2_XHI 0
#define G2_XLO 9216
#define G2_YHI 18432
#define G2_YLO 36864
#define G2_BIAS 55296
#define G2_SMEM 55808

__global__ __launch_bounds__(256) void g2(const float* __restrict__ x,
                                          const float* __restrict__ bias,
                                          float* __restrict__ out) {
    extern __shared__ char sm[];
    float* bias_s = (float*)(sm + G2_BIAS);
    const int tid = threadIdx.x, wid = tid >> 5, lane = tid & 31;
    const int st = blockIdx.x, b = blockIdx.y;
    const int s0 = st * 64;
    const int wm = wid & 3, wn = wid >> 2;
    const int s0w = wm * 16, o0w = wn * 64;

    const uint32_t s_xhi = smem_u32(sm + G2_XHI);
    const uint32_t s_xlo = smem_u32(sm + G2_XLO);
    const uint32_t s_yhi = smem_u32(sm + G2_YHI);
    const uint32_t s_ylo = smem_u32(sm + G2_YLO);

    // X tile [64 s][64 d] fp32 -> bf16 hi/lo
#pragma unroll
    for (int j = 0; j < 4; j++) {
        int idx = tid + j * 256;
        int s = idx >> 4, d4 = (idx & 15) * 4;
        float4 v = *(const float4*)(x + ((size_t)b * NS + s0 + s) * ND + d4);
        *(uint2*)(sm + G2_XHI + s * 144 + d4 * 2) =
            make_uint2(bpack2(v.x, v.y), bpack2(v.z, v.w));
        *(uint2*)(sm + G2_XLO + s * 144 + d4 * 2) =
            make_uint2(bpack2(blo(v.x), blo(v.y)), bpack2(blo(v.z), blo(v.w)));
    }
    // Y tile [128 o][64 d] bf16 (pre-split) copy
#pragma unroll
    for (int j = 0; j < 8; j++) {
        int idx = tid + j * 256;
        int o = idx >> 4, d4 = (idx & 15) * 4;
        size_t src = (size_t)(b * NO + o) * ND + d4;
        *(uint2*)(sm + G2_YHI + o * 144 + d4 * 2) = *(const uint2*)&g_yhi[src];
        *(uint2*)(sm + G2_YLO + o * 144 + d4 * 2) = *(const uint2*)&g_ylo[src];
    }
    if (tid < NO) bias_s[tid] = bias[tid];
    __syncthreads();

    float acc[8][4];
#pragma unroll
    for (int nt = 0; nt < 8; nt++)
#pragma unroll
        for (int q = 0; q < 4; q++) acc[nt][q] = 0.f;

#pragma unroll
    for (int kk = 0; kk < 4; kk++) {
        uint32_t ahi[4], alo[4];
        {
            uint32_t off = (uint32_t)((s0w + (lane & 15)) * 144 + kk * 32 +
                                      (lane >> 4) * 16);
            ldm_x4(ahi, s_xhi + off);
            ldm_x4(alo, s_xlo + off);
        }
        uint32_t bhi[4][4], blo_[4][4];
#pragma unroll
        for (int p = 0; p < 4; p++) {
            uint32_t off = (uint32_t)((o0w + p * 16 + (lane >> 4) * 8 + (lane & 7)) * 144 +
                                      kk * 32 + ((lane >> 3) & 1) * 16);
            ldm_x4(bhi[p], s_yhi + off);
            ldm_x4(blo_[p], s_ylo + off);
        }
#pragma unroll
        for (int nt = 0; nt < 8; nt++) {
            const uint32_t* bh = &bhi[nt >> 1][(nt & 1) * 2];
            const uint32_t* bl = &blo_[nt >> 1][(nt & 1) * 2];
            mma_bf16(acc[nt], ahi, bh);
            mma_bf16(acc[nt], ahi, bl);
            mma_bf16(acc[nt], alo, bh);
        }
    }

    // epilogue: +bias -> out
    const int srow = s0 + s0w + (lane >> 2);
#pragma unroll
    for (int nt = 0; nt < 8; nt++) {
        int o = o0w + nt * 8 + (lane & 3) * 2;
        float2 bb = *(float2*)&bias_s[o];
        float* p0 = out + ((size_t)b * NS + srow) * NO + o;
        *(float2*)p0 = make_float2(acc[nt][0] + bb.x, acc[nt][1] + bb.y);
        *(float2*)(p0 + 8 * NO) = make_float2(acc[nt][2] + bb.x, acc[nt][3] + bb.y);
    }
}

// ===========================================================================
extern "C" void kernel_launch(void* const* d_in, const int* in_sizes, int n_in,
                              void* d_out, int out_size) {
    const float* x = nullptr;
    const float* W = nullptr;
    const float* bias = nullptr;
    for (int i = 0; i < n_in; i++) {
        if (in_sizes[i] == NB * NS * ND)      x = (const float*)d_in[i];
        else if (in_sizes[i] == NO * NS)      W = (const float*)d_in[i];
        else if (in_sizes[i] == NO)           bias = (const float*)d_in[i];
    }
    float* out = (float*)d_out;

    cudaFuncSetAttribute(g1, cudaFuncAttributeMaxDynamicSharedMemorySize, G1_SMEM);
    cudaFuncSetAttribute(g2, cudaFuncAttributeMaxDynamicSharedMemorySize, G2_SMEM);

    g1<<<dim3(KSPLIT, NB), 256, G1_SMEM>>>(x, W);
    yred<<<(NB * NO * ND / 4) / 256, 256>>>();
    g2<<<dim3(NS / 64, NB), 256, G2_SMEM>>>(x, bias, out);
}

// round 6
// speedup vs baseline: 1.8876x; 1.2120x over previous
#include <cuda_runtime.h>
#include <cuda_bf16.h>
#include <cstdint>

#define NB 16
#define NS 2048
#define ND 64
#define NO 128
#define KSPLIT 16
#define KC 128            // K per g1 block (single stage)

// ---------------- scratch (no allocs allowed) ------------------------------
__device__ float         g_Ypart[KSPLIT * NB * NO * ND];   // 8 MB fp32 partials
__device__ __nv_bfloat16 g_yhi[NB * NO * ND];              // Y hi [b][o][d]
__device__ __nv_bfloat16 g_ylo[NB * NO * ND];              // Y lo

// ---------------- helpers --------------------------------------------------
__device__ __forceinline__ uint32_t smem_u32(const void* p) {
    uint32_t a;
    asm("{ .reg .u64 t; cvta.to.shared.u64 t, %1; cvt.u32.u64 %0, t; }"
        : "=r"(a) : "l"(p));
    return a;
}
__device__ __forceinline__ void ldm_x4(uint32_t* r, uint32_t addr) {
    asm volatile("ldmatrix.sync.aligned.m8n8.x4.shared.b16 {%0,%1,%2,%3}, [%4];"
                 : "=r"(r[0]), "=r"(r[1]), "=r"(r[2]), "=r"(r[3]) : "r"(addr));
}
__device__ __forceinline__ void ldm_x4t(uint32_t* r, uint32_t addr) {
    asm volatile("ldmatrix.sync.aligned.m8n8.x4.trans.shared.b16 {%0,%1,%2,%3}, [%4];"
                 : "=r"(r[0]), "=r"(r[1]), "=r"(r[2]), "=r"(r[3]) : "r"(addr));
}
__device__ __forceinline__ void mma_bf16(float* c, const uint32_t* a,
                                         const uint32_t* b) {
    asm volatile(
        "mma.sync.aligned.m16n8k16.row.col.f32.bf16.bf16.f32 "
        "{%0,%1,%2,%3}, {%4,%5,%6,%7}, {%8,%9}, {%0,%1,%2,%3};"
        : "+f"(c[0]), "+f"(c[1]), "+f"(c[2]), "+f"(c[3])
        : "r"(a[0]), "r"(a[1]), "r"(a[2]), "r"(a[3]), "r"(b[0]), "r"(b[1]));
}
__device__ __forceinline__ void cp_async16(uint32_t saddr, const void* g) {
    asm volatile("cp.async.cg.shared.global [%0], [%1], 16;"
                 :: "r"(saddr), "l"(g) : "memory");
}
#define CP_COMMIT() asm volatile("cp.async.commit_group;" ::: "memory")
#define CP_WAIT0()  asm volatile("cp.async.wait_group 0;" ::: "memory")

__device__ __forceinline__ uint32_t bpack2(float a, float b) {
    return (uint32_t)__bfloat16_as_ushort(__float2bfloat16(a)) |
           ((uint32_t)__bfloat16_as_ushort(__float2bfloat16(b)) << 16);
}
__device__ __forceinline__ float blo(float v) {
    return v - __bfloat162float(__float2bfloat16(v));
}

// ===========================================================================
// G1: Ypart[ks][b][o=128][d=64] = W[o, kslice] @ x[b, kslice, d]
// 3-term bf16 split via mma.sync. grid (KSPLIT=16, NB), 256 thr (8 warps 4x2),
// single K stage of 128. 2 CTAs/SM (smem 104KB, regs capped 128).
// smem: WA [128 o][136 k] hi/lo (pitch 272B), XB [128 k][72 d] hi/lo (144B).
// ===========================================================================
#define G1_WAHI 0
#define G1_WALO 34816
#define G1_XBHI 69632
#define G1_XBLO 88064
#define G1_SMEM 106496

__global__ __launch_bounds__(256, 2) void g1(const float* __restrict__ x,
                                             const float* __restrict__ W) {
    extern __shared__ char sm[];
    const int tid = threadIdx.x, wid = tid >> 5, lane = tid & 31;
    const int ks = blockIdx.x, b = blockIdx.y;
    const int wm = wid & 3, wn = wid >> 2;
    const int o0 = wm * 32, d0 = wn * 32;
    const int kbase = ks * KC;

    const uint32_t s_wahi = smem_u32(sm + G1_WAHI);
    const uint32_t s_walo = smem_u32(sm + G1_WALO);
    const uint32_t s_xbhi = smem_u32(sm + G1_XBHI);
    const uint32_t s_xblo = smem_u32(sm + G1_XBLO);

    // W tile [128 o][128 k] fp32 -> bf16 hi/lo
#pragma unroll
    for (int j = 0; j < 16; j++) {
        int idx = tid + j * 256;
        int o = idx >> 5, k4 = (idx & 31) * 4;
        float4 v = *(const float4*)(W + (size_t)o * NS + kbase + k4);
        *(uint2*)(sm + G1_WAHI + o * 272 + k4 * 2) =
            make_uint2(bpack2(v.x, v.y), bpack2(v.z, v.w));
        *(uint2*)(sm + G1_WALO + o * 272 + k4 * 2) =
            make_uint2(bpack2(blo(v.x), blo(v.y)), bpack2(blo(v.z), blo(v.w)));
    }
    // x tile [128 k][64 d] fp32 -> bf16 hi/lo
#pragma unroll
    for (int j = 0; j < 8; j++) {
        int idx = tid + j * 256;
        int k = idx >> 4, d4 = (idx & 15) * 4;
        float4 v = *(const float4*)(x + ((size_t)b * NS + kbase + k) * ND + d4);
        *(uint2*)(sm + G1_XBHI + k * 144 + d4 * 2) =
            make_uint2(bpack2(v.x, v.y), bpack2(v.z, v.w));
        *(uint2*)(sm + G1_XBLO + k * 144 + d4 * 2) =
            make_uint2(bpack2(blo(v.x), blo(v.y)), bpack2(blo(v.z), blo(v.w)));
    }
    __syncthreads();

    float acc[2][4][4];
#pragma unroll
    for (int mt = 0; mt < 2; mt++)
#pragma unroll
        for (int nt = 0; nt < 4; nt++)
#pragma unroll
            for (int q = 0; q < 4; q++) acc[mt][nt][q] = 0.f;

#pragma unroll
    for (int kk = 0; kk < 8; kk++) {
        uint32_t ahi[2][4], alo[2][4];
#pragma unroll
        for (int mt = 0; mt < 2; mt++) {
            uint32_t off = (uint32_t)((o0 + mt * 16 + (lane & 15)) * 272 +
                                      kk * 32 + (lane >> 4) * 16);
            ldm_x4(ahi[mt], s_wahi + off);
            ldm_x4(alo[mt], s_walo + off);
        }
        uint32_t bhi[2][4], blo_[2][4];
#pragma unroll
        for (int p = 0; p < 2; p++) {
            uint32_t off = (uint32_t)((kk * 16 + (lane & 15)) * 144 +
                                      (d0 + p * 16 + (lane >> 4) * 8) * 2);
            ldm_x4t(bhi[p], s_xbhi + off);
            ldm_x4t(blo_[p], s_xblo + off);
        }
#pragma unroll
        for (int mt = 0; mt < 2; mt++)
#pragma unroll
            for (int nt = 0; nt < 4; nt++) {
                const uint32_t* bh = &bhi[nt >> 1][(nt & 1) * 2];
                const uint32_t* bl = &blo_[nt >> 1][(nt & 1) * 2];
                mma_bf16(acc[mt][nt], ahi[mt], bh);
                mma_bf16(acc[mt][nt], ahi[mt], bl);
                mma_bf16(acc[mt][nt], alo[mt], bh);
            }
    }

    // epilogue -> Ypart fp32
    float* Yp = g_Ypart + ((size_t)(ks * NB + b) * NO) * ND;
#pragma unroll
    for (int mt = 0; mt < 2; mt++)
#pragma unroll
        for (int nt = 0; nt < 4; nt++) {
            int o = o0 + mt * 16 + (lane >> 2);
            int d = d0 + nt * 8 + (lane & 3) * 2;
            float* p = Yp + (size_t)o * ND + d;
            *(float2*)p = make_float2(acc[mt][nt][0], acc[mt][nt][1]);
            *(float2*)(p + 8 * ND) = make_float2(acc[mt][nt][2], acc[mt][nt][3]);
        }
}

// ===========================================================================
// Reduce partials -> Y bf16 hi/lo
// ===========================================================================
__global__ __launch_bounds__(256) void yred() {
    int e = blockIdx.x * 256 + threadIdx.x;   // float4 idx, 32768 total
    const float4* src = (const float4*)g_Ypart;
    const int stride = NB * NO * ND / 4;
    float4 s = src[e];
#pragma unroll
    for (int p = 1; p < KSPLIT; p++) {
        float4 v = src[(size_t)p * stride + e];
        s.x += v.x; s.y += v.y; s.z += v.z; s.w += v.w;
    }
    int base = e * 4;
    *(uint2*)&g_yhi[base] = make_uint2(bpack2(s.x, s.y), bpack2(s.z, s.w));
    *(uint2*)&g_ylo[base] = make_uint2(bpack2(blo(s.x), blo(s.y)),
                                       bpack2(blo(s.z), blo(s.w)));
}

// ===========================================================================
// G2: out[b][s][o] = x[b,s,:] . Y[b,o,:] + bias[o]
// grid (NS/64, NB) = 512 blocks, 256 thr (8 warps: 4 s x 2 o), 2 CTAs/SM.
// Tile M=64 s, N=128 o, K=64. Y tiles fetched via cp.async in 16B chunks
// (16B-aligned both sides: d8*2 bytes multiple of 16, pitch 144 = 9*16).
// ===========================================================================
#define G2_XHI 0
#define G2_XLO 9216
#define G2_YHI 18432
#define G2_YLO 36864
#define G2_BIAS 55296
#define G2_SMEM 55808

__global__ __launch_bounds__(256, 2) void g2(const float* __restrict__ x,
                                             const float* __restrict__ bias,
                                             float* __restrict__ out) {
    extern __shared__ char sm[];
    float* bias_s = (float*)(sm + G2_BIAS);
    const int tid = threadIdx.x, wid = tid >> 5, lane = tid & 31;
    const int st = blockIdx.x, b = blockIdx.y;
    const int s0 = st * 64;
    const int wm = wid & 3, wn = wid >> 2;
    const int s0w = wm * 16, o0w = wn * 64;

    const uint32_t s_xhi = smem_u32(sm + G2_XHI);
    const uint32_t s_xlo = smem_u32(sm + G2_XLO);
    const uint32_t s_yhi = smem_u32(sm + G2_YHI);
    const uint32_t s_ylo = smem_u32(sm + G2_YLO);

    // Y tiles (already bf16): async 16B copies, overlapped with X conversion.
    // idx covers 128 o x 8 chunks; o = idx>>3, d8 = (idx&7)*8 bf16 elements.
#pragma unroll
    for (int j = 0; j < 4; j++) {
        int idx = tid + j * 256;
        int o = idx >> 3, d8 = (idx & 7) * 8;
        size_t src = (size_t)(b * NO + o) * ND + d8;
        cp_async16(s_yhi + o * 144 + d8 * 2, &g_yhi[src]);
        cp_async16(s_ylo + o * 144 + d8 * 2, &g_ylo[src]);
    }
    CP_COMMIT();

    // X tile [64 s][64 d] fp32 -> bf16 hi/lo
#pragma unroll
    for (int j = 0; j < 4; j++) {
        int idx = tid + j * 256;
        int s = idx >> 4, d4 = (idx & 15) * 4;
        float4 v = *(const float4*)(x + ((size_t)b * NS + s0 + s) * ND + d4);
        *(uint2*)(sm + G2_XHI + s * 144 + d4 * 2) =
            make_uint2(bpack2(v.x, v.y), bpack2(v.z, v.w));
        *(uint2*)(sm + G2_XLO + s * 144 + d4 * 2) =
            make_uint2(bpack2(blo(v.x), blo(v.y)), bpack2(blo(v.z), blo(v.w)));
    }
    if (tid < NO) bias_s[tid] = bias[tid];
    CP_WAIT0();
    __syncthreads();

    float acc[8][4];
#pragma unroll
    for (int nt = 0; nt < 8; nt++)
#pragma unroll
        for (int q = 0; q < 4; q++) acc[nt][q] = 0.f;

#pragma unroll
    for (int kk = 0; kk < 4; kk++) {
        uint32_t ahi[4], alo[4];
        {
            uint32_t off = (uint32_t)((s0w + (lane & 15)) * 144 + kk * 32 +
                                      (lane >> 4) * 16);
            ldm_x4(ahi, s_xhi + off);
            ldm_x4(alo, s_xlo + off);
        }
        uint32_t bhi[4][4], blo_[4][4];
#pragma unroll
        for (int p = 0; p < 4; p++) {
            uint32_t off = (uint32_t)((o0w + p * 16 + (lane >> 4) * 8 + (lane & 7)) * 144 +
                                      kk * 32 + ((lane >> 3) & 1) * 16);
            ldm_x4(bhi[p], s_yhi + off);
            ldm_x4(blo_[p], s_ylo + off);
        }
#pragma unroll
        for (int nt = 0; nt < 8; nt++) {
            const uint32_t* bh = &bhi[nt >> 1][(nt & 1) * 2];
            const uint32_t* bl = &blo_[nt >> 1][(nt & 1) * 2];
            mma_bf16(acc[nt], ahi, bh);
            mma_bf16(acc[nt], ahi, bl);
            mma_bf16(acc[nt], alo, bh);
        }
    }

    // epilogue: +bias -> out
    const int srow = s0 + s0w + (lane >> 2);
#pragma unroll
    for (int nt = 0; nt < 8; nt++) {
        int o = o0w + nt * 8 + (lane & 3) * 2;
        float2 bb = *(float2*)&bias_s[o];
        float* p0 = out + ((size_t)b * NS + srow) * NO + o;
        *(float2*)p0 = make_float2(acc[nt][0] + bb.x, acc[nt][1] + bb.y);
        *(float2*)(p0 + 8 * NO) = make_float2(acc[nt][2] + bb.x, acc[nt][3] + bb.y);
    }
}

// ===========================================================================
extern "C" void kernel_launch(void* const* d_in, const int* in_sizes, int n_in,
                              void* d_out, int out_size) {
    const float* x = nullptr;
    const float* W = nullptr;
    const float* bias = nullptr;
    for (int i = 0; i < n_in; i++) {
        if (in_sizes[i] == NB * NS * ND)      x = (const float*)d_in[i];
        else if (in_sizes[i] == NO * NS)      W = (const float*)d_in[i];
        else if (in_sizes[i] == NO)           bias = (const float*)d_in[i];
    }
    float* out = (float*)d_out;

    cudaFuncSetAttribute(g1, cudaFuncAttributeMaxDynamicSharedMemorySize, G1_SMEM);
    cudaFuncSetAttribute(g2, cudaFuncAttributeMaxDynamicSharedMemorySize, G2_SMEM);

    g1<<<dim3(KSPLIT, NB), 256, G1_SMEM>>>(x, W);
    yred<<<(NB * NO * ND / 4) / 256, 256>>>();
    g2<<<dim3(NS / 64, NB), 256, G2_SMEM>>>(x, bias, out);
}